// round 14
// baseline (speedup 1.0000x reference)
#include <cuda_runtime.h>
#include <cuda.h>
#include <cuda_fp16.h>
#include <cstdint>
#include <cstddef>

// ---------------- problem dims (fixed) ----------------
#define TT 8192
#define KK 4096
#define NN 4096

#define TILE_M 128
#define TILE_N 256
#define TILE_K 128                 // k elements per chunk (2 x 64-col subtiles)
#define CPT 32                     // chunks per tile (KK / TILE_K)
#define NTILES 1024                // (TT/TILE_M) * (NN/TILE_N)
#define NCTA 148                   // persistent: one CTA per SM
#define NSTAGE 2

// stage: A 32KB (2 subtiles) | B 64KB (2 subtiles) = 98304
#define STAGE_BYTES 98304
#define A_SUB 16384
#define B_SUB 32768
#define OFF_TILE 1024
#define SMEM_TOTAL (OFF_TILE + NSTAGE * STAGE_BYTES)   // 197632 -> 1 CTA/SM

// mbarriers: full[s] at 16*s, empty[s] at 256+16*s
#define OFF_FULL(s)  (16 * (s))
#define OFF_EMPTY(s) (256 + 16 * (s))

// ---------------- scratch (device globals; no allocation) --------------
__device__ __half g_xh[(size_t)TT * KK];
__device__ __half g_wh[(size_t)NN * KK];

// ---------------- PTX helpers (non-'a' baseline only) -------------------
__device__ __forceinline__ uint32_t smem_u32(const void* p) {
    uint32_t a;
    asm("{ .reg .u64 t; cvta.to.shared.u64 t, %1; cvt.u32.u64 %0, t; }"
        : "=r"(a) : "l"(p));
    return a;
}

__device__ __forceinline__ void mbar_init(uint32_t addr, uint32_t count) {
    asm volatile("mbarrier.init.shared.b64 [%0], %1;" :: "r"(addr), "r"(count) : "memory");
}

__device__ __forceinline__ void mbar_expect_tx(uint32_t addr, uint32_t bytes) {
    asm volatile("mbarrier.arrive.expect_tx.shared.b64 _, [%0], %1;"
                 :: "r"(addr), "r"(bytes) : "memory");
}

__device__ __forceinline__ void mbar_arrive(uint32_t addr) {
    asm volatile("mbarrier.arrive.shared.b64 _, [%0];" :: "r"(addr) : "memory");
}

__device__ __forceinline__ void mbar_wait(uint32_t addr, uint32_t parity) {
    asm volatile(
        "{\n\t"
        ".reg .pred P;\n\t"
        "LAB_WAIT_%=:\n\t"
        "mbarrier.try_wait.parity.acquire.cta.shared::cta.b64 P, [%0], %1, 0x989680;\n\t"
        "@P bra LAB_DONE_%=;\n\t"
        "bra LAB_WAIT_%=;\n\t"
        "LAB_DONE_%=:\n\t"
        "}"
        :: "r"(addr), "r"(parity) : "memory");
}

__device__ __forceinline__ void tma_load3(uint32_t dst, const CUtensorMap* map,
                                          int cx, int cy, uint32_t mbar) {
    asm volatile(
        "cp.async.bulk.tensor.3d.shared::cta.global.tile.mbarrier::complete_tx::bytes "
        "[%0], [%1, {%2, %3, %4}], [%5];"
        :: "r"(dst), "l"(map), "r"(cx), "r"(cy), "r"(0), "r"(mbar)
        : "memory");
}

__device__ __forceinline__ void ldsm4(uint32_t* r, uint32_t addr) {
    asm volatile("ldmatrix.sync.aligned.m8n8.x4.shared.b16 {%0,%1,%2,%3}, [%4];"
                 : "=r"(r[0]), "=r"(r[1]), "=r"(r[2]), "=r"(r[3]) : "r"(addr));
}

__device__ __forceinline__ void mma_f16(float* c, const uint32_t* a,
                                        uint32_t b0, uint32_t b1) {
    asm volatile(
        "mma.sync.aligned.m16n8k16.row.col.f32.f16.f16.f32 "
        "{%0,%1,%2,%3}, {%4,%5,%6,%7}, {%8,%9}, {%0,%1,%2,%3};"
        : "+f"(c[0]), "+f"(c[1]), "+f"(c[2]), "+f"(c[3])
        : "r"(a[0]), "r"(a[1]), "r"(a[2]), "r"(a[3]), "r"(b0), "r"(b1));
}

// ---------------- fused prep kernel --------------------------------------
// act_quant round-trip is exact to fp32 rounding -> skipped; x converts to
// fp16 directly; w dequantizes (per 128x128 block scale) then converts.
#define XWORK (TT * KK / 8)        // 4194304
#define WWORK (NN * KK / 8)        // 2097152
#define PREPT (XWORK + WWORK)      // 6291456

__global__ void __launch_bounds__(256) prep_all(const float4* __restrict__ x,
                                                const float4* __restrict__ wq,
                                                const float* __restrict__ ws,
                                                uint4* __restrict__ xh,
                                                uint4* __restrict__ wh) {
    int i = blockIdx.x * blockDim.x + threadIdx.x;
    float4 v0, v1;
    uint4* dst;
    if (i < XWORK) {
        v0 = x[2 * (size_t)i];
        v1 = x[2 * (size_t)i + 1];
        dst = xh + i;
    } else {
        int j = i - XWORK;
        int e0 = j << 3;                       // element index in w
        int n = e0 >> 12;                      // / 4096
        int k = e0 & 4095;                     // 8 consecutive k, same 128-block
        float s = ws[(n >> 7) * (KK / 128) + (k >> 7)];
        v0 = wq[2 * (size_t)j];
        v1 = wq[2 * (size_t)j + 1];
        v0.x *= s; v0.y *= s; v0.z *= s; v0.w *= s;
        v1.x *= s; v1.y *= s; v1.z *= s; v1.w *= s;
        dst = wh + j;
    }
    __half2 h0 = __floats2half2_rn(v0.x, v0.y);
    __half2 h1 = __floats2half2_rn(v0.z, v0.w);
    __half2 h2 = __floats2half2_rn(v1.x, v1.y);
    __half2 h3 = __floats2half2_rn(v1.z, v1.w);
    uint4 o;
    o.x = *reinterpret_cast<uint32_t*>(&h0);
    o.y = *reinterpret_cast<uint32_t*>(&h1);
    o.z = *reinterpret_cast<uint32_t*>(&h2);
    o.w = *reinterpret_cast<uint32_t*>(&h3);
    *dst = o;
}

// ---------------- GEMM kernel --------------------------------------------
// Persistent: 148 CTAs, each loops over ~7 tiles; the full/empty stage ring
// spans tile boundaries so TMA for the next tile runs under the epilogue.
// CTA tile 128x256, 8 warps 2(M)x4(N), warp tile 64x64, TILE_K=128.
// R13-proven pipeline inside each chunk.

__device__ __forceinline__ void issue_chunk_g(uint32_t sb, int g, int bx,
                                              const CUtensorMap* pa,
                                              const CUtensorMap* pb) {
    int st = g & 1;
    int tl = bx + (g >> 5) * NCTA;          // tile id for this chunk
    int m0 = (tl >> 4) * TILE_M;
    int n0 = (tl & 15) * TILE_N;
    int k0 = (g & 31) * TILE_K;
    uint32_t mb = sb + OFF_FULL(st);
    mbar_expect_tx(mb, (uint32_t)STAGE_BYTES);
    uint32_t base = sb + OFF_TILE + st * STAGE_BYTES;
    tma_load3(base,                     pa, k0,      m0, mb);
    tma_load3(base + A_SUB,             pa, k0 + 64, m0, mb);
    tma_load3(base + 2 * A_SUB,         pb, k0,      n0, mb);
    tma_load3(base + 2 * A_SUB + B_SUB, pb, k0 + 64, n0, mb);
}

__global__ void __launch_bounds__(256, 1)
gemm_kernel(const __grid_constant__ CUtensorMap map_a,
            const __grid_constant__ CUtensorMap map_b,
            const float* __restrict__ bias,
            float* __restrict__ out) {
    extern __shared__ char smem[];
    uint32_t sb = smem_u32(smem);
    int tid = threadIdx.x;
    int l = tid & 31, wid = tid >> 5;
    int wm = wid >> 2, wn = wid & 3;        // 2 x 4 warp grid
    int bx = blockIdx.x;
    int ntiles = (NTILES - bx + NCTA - 1) / NCTA;   // 7 or 6
    int total = ntiles * CPT;

    if (tid == 0) {
        for (int s = 0; s < NSTAGE; s++) {
            mbar_init(sb + OFF_FULL(s), 1);
            mbar_init(sb + OFF_EMPTY(s), 8);
        }
        asm volatile("fence.proxy.async.shared::cta;" ::: "memory");
    }
    __syncthreads();

    if (tid == 0) {
        issue_chunk_g(sb, 0, bx, &map_a, &map_b);
        issue_chunk_g(sb, 1, bx, &map_a, &map_b);
    }

    // lane constants for swizzled ldmatrix addressing (rows are 128 bytes)
    int lm = l & 15;
    int lh = (l >> 4) << 4;                 // byte-column half: 0 or 16
    uint32_t xorv = (uint32_t)(lm & 7) << 4;
    uint32_t lob0 = ((uint32_t)lh) ^ xorv;  // ks=0 column offset
    uint32_t arow[4], brow[4];
#pragma unroll
    for (int mt = 0; mt < 4; mt++) arow[mt] = (uint32_t)(wm * 64 + mt * 16 + lm) * 128;
#pragma unroll
    for (int bt = 0; bt < 4; bt++) brow[bt] = (uint32_t)(wn * 64 + bt * 16 + lm) * 128;

    float acc[4][8][4] = {};
    uint32_t afr[4][4];            // A fragments, WAR-reused
    uint32_t bfr[2][4][4];         // B fragments, double-buffered [buf][bt][]

    // epilogue lane constants
    int g8 = l >> 2;               // row within m8 group
    int q = (l & 3) * 2;           // col pair within n8

    // prologue: wait chunk 0, load its ks=0 fragments
    uint32_t stA = sb + OFF_TILE;
    uint32_t stB = stA + 2 * A_SUB;
    mbar_wait(sb + OFF_FULL(0), 0);
#pragma unroll
    for (int mt = 0; mt < 4; mt++) ldsm4(afr[mt], stA + arow[mt] + lob0);
#pragma unroll
    for (int bt = 0; bt < 4; bt++) ldsm4(bfr[0][bt], stB + brow[bt] + lob0);

#pragma unroll 1
    for (int g = 0; g < total; g++) {
        int st = g & 1;
        uint32_t ph = (uint32_t)((g >> 1) & 1);

#pragma unroll
        for (int ks = 0; ks < 8; ks++) {
            int cb = ks & 1, nb = cb ^ 1;
            int kn = ks + 1;
            uint32_t subA = (uint32_t)(kn >> 2) * A_SUB;
            uint32_t subB = (uint32_t)(kn >> 2) * B_SUB;
            uint32_t lobn = ((uint32_t)(lh + (kn & 3) * 32)) ^ xorv;

            if (ks < 7) {
#pragma unroll
                for (int bt = 0; bt < 4; bt++)
                    ldsm4(bfr[nb][bt], stB + subB + brow[bt] + lobn);
            } else {
                if (l == 0) mbar_arrive(sb + OFF_EMPTY(st));
            }

#pragma unroll
            for (int mt = 0; mt < 4; mt++) {
#pragma unroll
                for (int nt = 0; nt < 8; nt++) {
                    int bt = nt >> 1, se = nt & 1;
                    mma_f16(acc[mt][nt], afr[mt], bfr[cb][bt][se], bfr[cb][bt][se + 2]);
                }
                if (ks < 7) ldsm4(afr[mt], stA + subA + arow[mt] + lobn);
            }
        }

        // producer: refill this stage once all 8 warps drained it.
        // chunk g+2 shares stage with g; may belong to the NEXT tile —
        // that's the point: TMA runs under the coming epilogue.
        if (tid == 0 && g + 2 < total) {
            mbar_wait(sb + OFF_EMPTY(st), ph);
            issue_chunk_g(sb, g + 2, bx, &map_a, &map_b);
        }

        // tile finished: epilogue while next tile's TMA is in flight
        if ((g & 31) == 31) {
            int tl = bx + (g >> 5) * NCTA;
            int m0 = (tl >> 4) * TILE_M;
            int n0 = (tl & 15) * TILE_N;
#pragma unroll
            for (int mt = 0; mt < 4; mt++) {
                int r0 = m0 + wm * 64 + mt * 16 + g8;
#pragma unroll
                for (int nt = 0; nt < 8; nt++) {
                    int col = n0 + wn * 64 + nt * 8 + q;
                    float2 bv = *reinterpret_cast<const float2*>(bias + col);
                    float2 v0, v1;
                    v0.x = acc[mt][nt][0] + bv.x;
                    v0.y = acc[mt][nt][1] + bv.y;
                    v1.x = acc[mt][nt][2] + bv.x;
                    v1.y = acc[mt][nt][3] + bv.y;
                    *reinterpret_cast<float2*>(out + (size_t)r0 * NN + col) = v0;
                    *reinterpret_cast<float2*>(out + (size_t)(r0 + 8) * NN + col) = v1;
                    acc[mt][nt][0] = 0.f; acc[mt][nt][1] = 0.f;
                    acc[mt][nt][2] = 0.f; acc[mt][nt][3] = 0.f;
                }
            }
        }

        // advance: wait next chunk full, load its ks=0 fragments
        if (g + 1 < total) {
            int st2 = (g + 1) & 1;
            uint32_t ph2 = (uint32_t)(((g + 1) >> 1) & 1);
            stA = sb + OFF_TILE + st2 * STAGE_BYTES;
            stB = stA + 2 * A_SUB;
            mbar_wait(sb + OFF_FULL(st2), ph2);
#pragma unroll
            for (int mt = 0; mt < 4; mt++) ldsm4(afr[mt], stA + arow[mt] + lob0);
#pragma unroll
            for (int bt = 0; bt < 4; bt++) ldsm4(bfr[0][bt], stB + brow[bt] + lob0);
        }
    }
}

// ---------------- host launch ---------------------------------------------
typedef CUresult (*PFN_encodeTiled)(CUtensorMap*, CUtensorMapDataType, cuuint32_t,
                                    void*, const cuuint64_t*, const cuuint64_t*,
                                    const cuuint32_t*, const cuuint32_t*,
                                    CUtensorMapInterleave, CUtensorMapSwizzle,
                                    CUtensorMapL2promotion, CUtensorMapFloatOOBfill);

static void encode_map(PFN_encodeTiled enc, CUtensorMap* m, void* ptr,
                       unsigned long long d0, unsigned long long d1,
                       unsigned b0, unsigned b1) {
    cuuint64_t dims[3]    = {d0, d1, 1};
    cuuint64_t strides[2] = {d0 * 2ull, d0 * d1 * 2ull};   // fp16
    cuuint32_t box[3]     = {b0, b1, 1};
    cuuint32_t es[3]      = {1, 1, 1};
    enc(m, CU_TENSOR_MAP_DATA_TYPE_FLOAT16, 3, ptr, dims, strides, box, es,
        CU_TENSOR_MAP_INTERLEAVE_NONE, CU_TENSOR_MAP_SWIZZLE_128B,
        CU_TENSOR_MAP_L2_PROMOTION_L2_128B, CU_TENSOR_MAP_FLOAT_OOB_FILL_NONE);
}

extern "C" void kernel_launch(void* const* d_in, const int* in_sizes, int n_in,
                              void* d_out, int out_size) {
    const float* x    = (const float*)d_in[0];
    const float* wq   = (const float*)d_in[1];
    const float* ws   = (const float*)d_in[2];
    const float* bias = (const float*)d_in[3];
    float* out = (float*)d_out;

    void *pxh, *pwh;
    cudaGetSymbolAddress(&pxh, g_xh);
    cudaGetSymbolAddress(&pwh, g_wh);

    prep_all<<<PREPT / 256, 256>>>((const float4*)x, (const float4*)wq, ws,
                                   (uint4*)pxh, (uint4*)pwh);

    void* fn = nullptr;
    cudaDriverEntryPointQueryResult qr;
    cudaGetDriverEntryPointByVersion("cuTensorMapEncodeTiled", &fn, 12000,
                                     cudaEnableDefault, &qr);
    PFN_encodeTiled enc = (PFN_encodeTiled)fn;

    CUtensorMap ma, mb;
    encode_map(enc, &ma, pxh, KK, TT, 64, TILE_M);
    encode_map(enc, &mb, pwh, KK, NN, 64, TILE_N);

    cudaFuncSetAttribute(gemm_kernel, cudaFuncAttributeMaxDynamicSharedMemorySize,
                         SMEM_TOTAL);
    gemm_kernel<<<NCTA, 256, SMEM_TOTAL>>>(ma, mb, bias, out);
}

// round 15
// speedup vs baseline: 1.1388x; 1.1388x over previous
#include <cuda_runtime.h>
#include <cuda.h>
#include <cuda_fp16.h>
#include <cstdint>
#include <cstddef>

// ---------------- problem dims (fixed) ----------------
#define TT 8192
#define KK 4096
#define NN 4096

#define TILE_M 128
#define TILE_N 256
#define TILE_K 128                 // k elements per chunk (2 x 64-col subtiles)
#define NCHUNK (KK / TILE_K)       // 32
#define NSTAGE 2

// stage: A 32KB (2 subtiles) | B 64KB (2 subtiles) = 98304
#define STAGE_BYTES 98304
#define A_SUB 16384
#define B_SUB 32768
#define OFF_TILE 1024
#define SMEM_TOTAL (OFF_TILE + NSTAGE * STAGE_BYTES)   // 197632 -> 1 CTA/SM

// mbarriers: full[s] at 16*s, empty[s] at 256+16*s
#define OFF_FULL(s)  (16 * (s))
#define OFF_EMPTY(s) (256 + 16 * (s))

// ---------------- scratch (device globals; no allocation) --------------
__device__ __half g_xh[(size_t)TT * KK];
__device__ __half g_wh[(size_t)NN * KK];

// ---------------- PTX helpers (non-'a' baseline only) -------------------
__device__ __forceinline__ uint32_t smem_u32(const void* p) {
    uint32_t a;
    asm("{ .reg .u64 t; cvta.to.shared.u64 t, %1; cvt.u32.u64 %0, t; }"
        : "=r"(a) : "l"(p));
    return a;
}

__device__ __forceinline__ void mbar_init(uint32_t addr, uint32_t count) {
    asm volatile("mbarrier.init.shared.b64 [%0], %1;" :: "r"(addr), "r"(count) : "memory");
}

__device__ __forceinline__ void mbar_expect_tx(uint32_t addr, uint32_t bytes) {
    asm volatile("mbarrier.arrive.expect_tx.shared.b64 _, [%0], %1;"
                 :: "r"(addr), "r"(bytes) : "memory");
}

__device__ __forceinline__ void mbar_arrive(uint32_t addr) {
    asm volatile("mbarrier.arrive.shared.b64 _, [%0];" :: "r"(addr) : "memory");
}

__device__ __forceinline__ void mbar_wait(uint32_t addr, uint32_t parity) {
    asm volatile(
        "{\n\t"
        ".reg .pred P;\n\t"
        "LAB_WAIT_%=:\n\t"
        "mbarrier.try_wait.parity.acquire.cta.shared::cta.b64 P, [%0], %1, 0x989680;\n\t"
        "@P bra LAB_DONE_%=;\n\t"
        "bra LAB_WAIT_%=;\n\t"
        "LAB_DONE_%=:\n\t"
        "}"
        :: "r"(addr), "r"(parity) : "memory");
}

__device__ __forceinline__ void tma_load3(uint32_t dst, const CUtensorMap* map,
                                          int cx, int cy, uint32_t mbar) {
    asm volatile(
        "cp.async.bulk.tensor.3d.shared::cta.global.tile.mbarrier::complete_tx::bytes "
        "[%0], [%1, {%2, %3, %4}], [%5];"
        :: "r"(dst), "l"(map), "r"(cx), "r"(cy), "r"(0), "r"(mbar)
        : "memory");
}

__device__ __forceinline__ void ldsm4(uint32_t* r, uint32_t addr) {
    asm volatile("ldmatrix.sync.aligned.m8n8.x4.shared.b16 {%0,%1,%2,%3}, [%4];"
                 : "=r"(r[0]), "=r"(r[1]), "=r"(r[2]), "=r"(r[3]) : "r"(addr));
}

__device__ __forceinline__ void mma_f16(float* c, const uint32_t* a,
                                        uint32_t b0, uint32_t b1) {
    asm volatile(
        "mma.sync.aligned.m16n8k16.row.col.f32.f16.f16.f32 "
        "{%0,%1,%2,%3}, {%4,%5,%6,%7}, {%8,%9}, {%0,%1,%2,%3};"
        : "+f"(c[0]), "+f"(c[1]), "+f"(c[2]), "+f"(c[3])
        : "r"(a[0]), "r"(a[1]), "r"(a[2]), "r"(a[3]), "r"(b0), "r"(b1));
}

// ---------------- fused prep kernel --------------------------------------
// act_quant round-trip is exact to fp32 rounding -> skipped; x converts to
// fp16 directly; w dequantizes (per 128x128 block scale) then converts.
#define XWORK (TT * KK / 8)        // 4194304
#define WWORK (NN * KK / 8)        // 2097152
#define PREPT (XWORK + WWORK)      // 6291456

__global__ void __launch_bounds__(256) prep_all(const float4* __restrict__ x,
                                                const float4* __restrict__ wq,
                                                const float* __restrict__ ws,
                                                uint4* __restrict__ xh,
                                                uint4* __restrict__ wh) {
    int i = blockIdx.x * blockDim.x + threadIdx.x;
    float4 v0, v1;
    uint4* dst;
    if (i < XWORK) {
        v0 = x[2 * (size_t)i];
        v1 = x[2 * (size_t)i + 1];
        dst = xh + i;
    } else {
        int j = i - XWORK;
        int e0 = j << 3;                       // element index in w
        int n = e0 >> 12;                      // / 4096
        int k = e0 & 4095;                     // 8 consecutive k, same 128-block
        float s = ws[(n >> 7) * (KK / 128) + (k >> 7)];
        v0 = wq[2 * (size_t)j];
        v1 = wq[2 * (size_t)j + 1];
        v0.x *= s; v0.y *= s; v0.z *= s; v0.w *= s;
        v1.x *= s; v1.y *= s; v1.z *= s; v1.w *= s;
        dst = wh + j;
    }
    __half2 h0 = __floats2half2_rn(v0.x, v0.y);
    __half2 h1 = __floats2half2_rn(v0.z, v0.w);
    __half2 h2 = __floats2half2_rn(v1.x, v1.y);
    __half2 h3 = __floats2half2_rn(v1.z, v1.w);
    uint4 o;
    o.x = *reinterpret_cast<uint32_t*>(&h0);
    o.y = *reinterpret_cast<uint32_t*>(&h1);
    o.z = *reinterpret_cast<uint32_t*>(&h2);
    o.w = *reinterpret_cast<uint32_t*>(&h3);
    *dst = o;
}

// ---------------- GEMM kernel --------------------------------------------
// CTA 128x256, 256 threads, 8 warps 2(M) x 4(N); warp tile 64x64. 1 CTA/SM.
// TILE_K=128 (8 ks iters). R13 pipeline with two boundary refinements:
//  - producer role ROTATES: chunk c+2 issued by warp (c+2)&7 (stall spreads
//    across SMSPs instead of always hitting warp 0 / SMSP 0)
//  - boundary reordered: frag loads for next chunk FIRST, then empty-wait +
//    TMA issue (producer enters next chunk's mma stream immediately)

__device__ __forceinline__ void issue_chunk(uint32_t sb, int c, int m0, int n0,
                                            const CUtensorMap* pa,
                                            const CUtensorMap* pb) {
    int st = c % NSTAGE;
    uint32_t mb = sb + OFF_FULL(st);
    mbar_expect_tx(mb, (uint32_t)STAGE_BYTES);
    int k0 = c * TILE_K;
    uint32_t base = sb + OFF_TILE + st * STAGE_BYTES;
    tma_load3(base,                     pa, k0,      m0, mb);
    tma_load3(base + A_SUB,             pa, k0 + 64, m0, mb);
    tma_load3(base + 2 * A_SUB,         pb, k0,      n0, mb);
    tma_load3(base + 2 * A_SUB + B_SUB, pb, k0 + 64, n0, mb);
}

__global__ void __launch_bounds__(256, 1)
gemm_kernel(const __grid_constant__ CUtensorMap map_a,
            const __grid_constant__ CUtensorMap map_b,
            const float* __restrict__ bias,
            float* __restrict__ out) {
    extern __shared__ char smem[];
    uint32_t sb = smem_u32(smem);
    int tid = threadIdx.x;
    int l = tid & 31, wid = tid >> 5;
    int wm = wid >> 2, wn = wid & 3;        // 2 x 4 warp grid
    int m0 = blockIdx.y * TILE_M;
    int n0 = blockIdx.x * TILE_N;

    if (tid == 0) {
        for (int s = 0; s < NSTAGE; s++) {
            mbar_init(sb + OFF_FULL(s), 1);
            mbar_init(sb + OFF_EMPTY(s), 8);
        }
        asm volatile("fence.proxy.async.shared::cta;" ::: "memory");
    }
    __syncthreads();

    if (tid == 0) {
        issue_chunk(sb, 0, m0, n0, &map_a, &map_b);
        issue_chunk(sb, 1, m0, n0, &map_a, &map_b);
    }

    // lane constants for swizzled ldmatrix addressing (rows are 128 bytes)
    int lm = l & 15;
    int lh = (l >> 4) << 4;                 // byte-column half: 0 or 16
    uint32_t xorv = (uint32_t)(lm & 7) << 4;
    uint32_t lob0 = ((uint32_t)lh) ^ xorv;  // ks=0 column offset
    uint32_t arow[4], brow[4];
#pragma unroll
    for (int mt = 0; mt < 4; mt++) arow[mt] = (uint32_t)(wm * 64 + mt * 16 + lm) * 128;
#pragma unroll
    for (int bt = 0; bt < 4; bt++) brow[bt] = (uint32_t)(wn * 64 + bt * 16 + lm) * 128;

    float acc[4][8][4] = {};
    uint32_t afr[4][4];            // A fragments, WAR-reused
    uint32_t bfr[2][4][4];         // B fragments, double-buffered [buf][bt][]

    // prologue: wait chunk 0, load its ks=0 fragments
    uint32_t stA = sb + OFF_TILE;           // stage 0 A base (2 subtiles)
    uint32_t stB = stA + 2 * A_SUB;         // stage 0 B base (2 subtiles)
    mbar_wait(sb + OFF_FULL(0), 0);
#pragma unroll
    for (int mt = 0; mt < 4; mt++) ldsm4(afr[mt], stA + arow[mt] + lob0);
#pragma unroll
    for (int bt = 0; bt < 4; bt++) ldsm4(bfr[0][bt], stB + brow[bt] + lob0);

    for (int c = 0; c < NCHUNK; c++) {
        int st = c % NSTAGE;
        uint32_t ph = (uint32_t)((c / NSTAGE) & 1);

#pragma unroll
        for (int ks = 0; ks < 8; ks++) {
            int cb = ks & 1, nb = cb ^ 1;
            int kn = ks + 1;                            // next ks (1..8)
            uint32_t subA = (uint32_t)(kn >> 2) * A_SUB;  // next subtile offs
            uint32_t subB = (uint32_t)(kn >> 2) * B_SUB;
            uint32_t lobn = ((uint32_t)(lh + (kn & 3) * 32)) ^ xorv;

            if (ks < 7) {
                // prefetch next ks B fragments (consumed next iteration)
#pragma unroll
                for (int bt = 0; bt < 4; bt++)
                    ldsm4(bfr[nb][bt], stB + subB + brow[bt] + lobn);
            } else {
                // all reads from this stage done (ks=7 frags loaded at ks=6)
                if (l == 0) mbar_arrive(sb + OFF_EMPTY(st));
            }

#pragma unroll
            for (int mt = 0; mt < 4; mt++) {
#pragma unroll
                for (int nt = 0; nt < 8; nt++) {
                    int bt = nt >> 1, se = nt & 1;
                    mma_f16(acc[mt][nt], afr[mt], bfr[cb][bt][se], bfr[cb][bt][se + 2]);
                }
                if (ks < 7) ldsm4(afr[mt], stA + subA + arow[mt] + lobn);  // WAR
            }
        }

        // advance to next chunk FIRST: wait full, load its ks=0 fragments
        if (c + 1 < NCHUNK) {
            int st2 = (c + 1) % NSTAGE;
            uint32_t ph2 = (uint32_t)(((c + 1) / NSTAGE) & 1);
            stA = sb + OFF_TILE + st2 * STAGE_BYTES;
            stB = stA + 2 * A_SUB;
            mbar_wait(sb + OFF_FULL(st2), ph2);
#pragma unroll
            for (int mt = 0; mt < 4; mt++) ldsm4(afr[mt], stA + arow[mt] + lob0);
#pragma unroll
            for (int bt = 0; bt < 4; bt++) ldsm4(bfr[0][bt], stB + brow[bt] + lob0);
        }

        // rotating producer: warp (c+2)&7 refills stage st with chunk c+2
        // after all 8 warps drained it (they arrive at their own ks=7)
        if (c + 2 < NCHUNK && wid == ((c + 2) & 7) && l == 0) {
            mbar_wait(sb + OFF_EMPTY(st), ph);
            issue_chunk(sb, c + 2, m0, n0, &map_a, &map_b);
        }
    }

    // epilogue: bias add + fp32 stores (mma C-frag layout)
    int g = l >> 2;                // row within m8 group
    int q = (l & 3) * 2;           // col pair within n8
#pragma unroll
    for (int mt = 0; mt < 4; mt++) {
        int r0 = m0 + wm * 64 + mt * 16 + g;
#pragma unroll
        for (int nt = 0; nt < 8; nt++) {
            int col = n0 + wn * 64 + nt * 8 + q;
            float2 bv = *reinterpret_cast<const float2*>(bias + col);
            float2 v0, v1;
            v0.x = acc[mt][nt][0] + bv.x;
            v0.y = acc[mt][nt][1] + bv.y;
            v1.x = acc[mt][nt][2] + bv.x;
            v1.y = acc[mt][nt][3] + bv.y;
            *reinterpret_cast<float2*>(out + (size_t)r0 * NN + col) = v0;
            *reinterpret_cast<float2*>(out + (size_t)(r0 + 8) * NN + col) = v1;
        }
    }
}

// ---------------- host launch ---------------------------------------------
typedef CUresult (*PFN_encodeTiled)(CUtensorMap*, CUtensorMapDataType, cuuint32_t,
                                    void*, const cuuint64_t*, const cuuint64_t*,
                                    const cuuint32_t*, const cuuint32_t*,
                                    CUtensorMapInterleave, CUtensorMapSwizzle,
                                    CUtensorMapL2promotion, CUtensorMapFloatOOBfill);

static void encode_map(PFN_encodeTiled enc, CUtensorMap* m, void* ptr,
                       unsigned long long d0, unsigned long long d1,
                       unsigned b0, unsigned b1) {
    cuuint64_t dims[3]    = {d0, d1, 1};
    cuuint64_t strides[2] = {d0 * 2ull, d0 * d1 * 2ull};   // fp16
    cuuint32_t box[3]     = {b0, b1, 1};
    cuuint32_t es[3]      = {1, 1, 1};
    enc(m, CU_TENSOR_MAP_DATA_TYPE_FLOAT16, 3, ptr, dims, strides, box, es,
        CU_TENSOR_MAP_INTERLEAVE_NONE, CU_TENSOR_MAP_SWIZZLE_128B,
        CU_TENSOR_MAP_L2_PROMOTION_L2_128B, CU_TENSOR_MAP_FLOAT_OOB_FILL_NONE);
}

extern "C" void kernel_launch(void* const* d_in, const int* in_sizes, int n_in,
                              void* d_out, int out_size) {
    const float* x    = (const float*)d_in[0];
    const float* wq   = (const float*)d_in[1];
    const float* ws   = (const float*)d_in[2];
    const float* bias = (const float*)d_in[3];
    float* out = (float*)d_out;

    void *pxh, *pwh;
    cudaGetSymbolAddress(&pxh, g_xh);
    cudaGetSymbolAddress(&pwh, g_wh);

    prep_all<<<PREPT / 256, 256>>>((const float4*)x, (const float4*)wq, ws,
                                   (uint4*)pxh, (uint4*)pwh);

    void* fn = nullptr;
    cudaDriverEntryPointQueryResult qr;
    cudaGetDriverEntryPointByVersion("cuTensorMapEncodeTiled", &fn, 12000,
                                     cudaEnableDefault, &qr);
    PFN_encodeTiled enc = (PFN_encodeTiled)fn;

    CUtensorMap ma, mb;
    encode_map(enc, &ma, pxh, KK, TT, 64, TILE_M);
    encode_map(enc, &mb, pwh, KK, NN, 64, TILE_N);

    cudaFuncSetAttribute(gemm_kernel, cudaFuncAttributeMaxDynamicSharedMemorySize,
                         SMEM_TOTAL);
    dim3 grid(NN / TILE_N, TT / TILE_M);   // 16 x 64
    gemm_kernel<<<grid, 256, SMEM_TOTAL>>>(ma, mb, bias, out);
}

// round 16
// speedup vs baseline: 1.1714x; 1.0286x over previous
#include <cuda_runtime.h>
#include <cuda.h>
#include <cuda_fp16.h>
#include <cstdint>
#include <cstddef>

// ---------------- problem dims (fixed) ----------------
#define TT 8192
#define KK 4096
#define NN 4096

#define TILE_M 128
#define TILE_N 256
#define TILE_K 128                 // k elements per chunk (2 x 64-col subtiles)
#define CPT 32                     // chunks per tile
#define NTILES 1024
#define NCTA 148
#define NSTAGE 2

// stage: A 32KB (2 subtiles) | B 64KB (2 subtiles) = 98304
#define STAGE_BYTES 98304
#define A_SUB 16384
#define B_SUB 32768
#define OFF_TILE 1024
#define SMEM_TOTAL (OFF_TILE + NSTAGE * STAGE_BYTES)   // 197632 -> 1 CTA/SM

// mbarriers: full[s] at 16*s, empty[s] at 256+16*s
#define OFF_FULL(s)  (16 * (s))
#define OFF_EMPTY(s) (256 + 16 * (s))

// ---------------- scratch (device globals; no allocation) --------------
__device__ __half g_xh[(size_t)TT * KK];
__device__ __half g_wh[(size_t)NN * KK];

// ---------------- PTX helpers (non-'a' baseline only) -------------------
__device__ __forceinline__ uint32_t smem_u32(const void* p) {
    uint32_t a;
    asm("{ .reg .u64 t; cvta.to.shared.u64 t, %1; cvt.u32.u64 %0, t; }"
        : "=r"(a) : "l"(p));
    return a;
}

__device__ __forceinline__ void mbar_init(uint32_t addr, uint32_t count) {
    asm volatile("mbarrier.init.shared.b64 [%0], %1;" :: "r"(addr), "r"(count) : "memory");
}

__device__ __forceinline__ void mbar_expect_tx(uint32_t addr, uint32_t bytes) {
    asm volatile("mbarrier.arrive.expect_tx.shared.b64 _, [%0], %1;"
                 :: "r"(addr), "r"(bytes) : "memory");
}

__device__ __forceinline__ void mbar_arrive(uint32_t addr) {
    asm volatile("mbarrier.arrive.shared.b64 _, [%0];" :: "r"(addr) : "memory");
}

__device__ __forceinline__ void mbar_wait(uint32_t addr, uint32_t parity) {
    asm volatile(
        "{\n\t"
        ".reg .pred P;\n\t"
        "LAB_WAIT_%=:\n\t"
        "mbarrier.try_wait.parity.acquire.cta.shared::cta.b64 P, [%0], %1, 0x989680;\n\t"
        "@P bra LAB_DONE_%=;\n\t"
        "bra LAB_WAIT_%=;\n\t"
        "LAB_DONE_%=:\n\t"
        "}"
        :: "r"(addr), "r"(parity) : "memory");
}

__device__ __forceinline__ void tma_load3(uint32_t dst, const CUtensorMap* map,
                                          int cx, int cy, uint32_t mbar) {
    asm volatile(
        "cp.async.bulk.tensor.3d.shared::cta.global.tile.mbarrier::complete_tx::bytes "
        "[%0], [%1, {%2, %3, %4}], [%5];"
        :: "r"(dst), "l"(map), "r"(cx), "r"(cy), "r"(0), "r"(mbar)
        : "memory");
}

__device__ __forceinline__ void ldsm4(uint32_t* r, uint32_t addr) {
    asm volatile("ldmatrix.sync.aligned.m8n8.x4.shared.b16 {%0,%1,%2,%3}, [%4];"
                 : "=r"(r[0]), "=r"(r[1]), "=r"(r[2]), "=r"(r[3]) : "r"(addr));
}

__device__ __forceinline__ void mma_f16(float* c, const uint32_t* a,
                                        uint32_t b0, uint32_t b1) {
    asm volatile(
        "mma.sync.aligned.m16n8k16.row.col.f32.f16.f16.f32 "
        "{%0,%1,%2,%3}, {%4,%5,%6,%7}, {%8,%9}, {%0,%1,%2,%3};"
        : "+f"(c[0]), "+f"(c[1]), "+f"(c[2]), "+f"(c[3])
        : "r"(a[0]), "r"(a[1]), "r"(a[2]), "r"(a[3]), "r"(b0), "r"(b1));
}

// ---------------- fused prep kernel --------------------------------------
// act_quant round-trip is exact to fp32 rounding -> skipped; x converts to
// fp16 directly; w dequantizes (per 128x128 block scale) then converts.
#define XWORK (TT * KK / 8)        // 4194304
#define WWORK (NN * KK / 8)        // 2097152
#define PREPT (XWORK + WWORK)      // 6291456

__global__ void __launch_bounds__(256) prep_all(const float4* __restrict__ x,
                                                const float4* __restrict__ wq,
                                                const float* __restrict__ ws,
                                                uint4* __restrict__ xh,
                                                uint4* __restrict__ wh) {
    int i = blockIdx.x * blockDim.x + threadIdx.x;
    float4 v0, v1;
    uint4* dst;
    if (i < XWORK) {
        v0 = x[2 * (size_t)i];
        v1 = x[2 * (size_t)i + 1];
        dst = xh + i;
    } else {
        int j = i - XWORK;
        int e0 = j << 3;                       // element index in w
        int n = e0 >> 12;                      // / 4096
        int k = e0 & 4095;                     // 8 consecutive k, same 128-block
        float s = ws[(n >> 7) * (KK / 128) + (k >> 7)];
        v0 = wq[2 * (size_t)j];
        v1 = wq[2 * (size_t)j + 1];
        v0.x *= s; v0.y *= s; v0.z *= s; v0.w *= s;
        v1.x *= s; v1.y *= s; v1.z *= s; v1.w *= s;
        dst = wh + j;
    }
    __half2 h0 = __floats2half2_rn(v0.x, v0.y);
    __half2 h1 = __floats2half2_rn(v0.z, v0.w);
    __half2 h2 = __floats2half2_rn(v1.x, v1.y);
    __half2 h3 = __floats2half2_rn(v1.z, v1.w);
    uint4 o;
    o.x = *reinterpret_cast<uint32_t*>(&h0);
    o.y = *reinterpret_cast<uint32_t*>(&h1);
    o.z = *reinterpret_cast<uint32_t*>(&h2);
    o.w = *reinterpret_cast<uint32_t*>(&h3);
    *dst = o;
}

// ---------------- GEMM kernel --------------------------------------------
// Persistent (148 CTAs, ~7 tiles each) with R13's chunk loop kept intact:
// outer tile loop, inner 32-chunk loop, epilogue OUTSIDE the chunk loop.
// CPT=32 is even -> stage (c&1) and parities ((c>>1)&1) are tile-invariant;
// the full/empty ring continues seamlessly across tiles. Producers at
// c=30,31 issue the NEXT tile's chunks 0,1 so its TMA flies under the
// epilogue; the post-epilogue boundary wait is then fast-path.

__device__ __forceinline__ void issue_chunk(uint32_t sb, int st, int k0,
                                            int m0, int n0,
                                            const CUtensorMap* pa,
                                            const CUtensorMap* pb) {
    uint32_t mb = sb + OFF_FULL(st);
    mbar_expect_tx(mb, (uint32_t)STAGE_BYTES);
    uint32_t base = sb + OFF_TILE + st * STAGE_BYTES;
    tma_load3(base,                     pa, k0,      m0, mb);
    tma_load3(base + A_SUB,             pa, k0 + 64, m0, mb);
    tma_load3(base + 2 * A_SUB,         pb, k0,      n0, mb);
    tma_load3(base + 2 * A_SUB + B_SUB, pb, k0 + 64, n0, mb);
}

__global__ void __launch_bounds__(256, 1)
gemm_kernel(const __grid_constant__ CUtensorMap map_a,
            const __grid_constant__ CUtensorMap map_b,
            const float* __restrict__ bias,
            float* __restrict__ out) {
    extern __shared__ char smem[];
    uint32_t sb = smem_u32(smem);
    int tid = threadIdx.x;
    int l = tid & 31, wid = tid >> 5;
    int wm = wid >> 2, wn = wid & 3;        // 2 x 4 warp grid
    int bx = blockIdx.x;
    int ntiles = (NTILES - bx + NCTA - 1) / NCTA;

    if (tid == 0) {
        for (int s = 0; s < NSTAGE; s++) {
            mbar_init(sb + OFF_FULL(s), 1);
            mbar_init(sb + OFF_EMPTY(s), 8);
        }
        asm volatile("fence.proxy.async.shared::cta;" ::: "memory");
    }
    __syncthreads();

    int tl = bx;
    int m0 = (tl >> 4) * TILE_M;
    int n0 = (tl & 15) * TILE_N;

    if (tid == 0) {
        issue_chunk(sb, 0, 0,      m0, n0, &map_a, &map_b);
        issue_chunk(sb, 1, TILE_K, m0, n0, &map_a, &map_b);
    }

    // lane constants for swizzled ldmatrix addressing (rows are 128 bytes)
    int lm = l & 15;
    int lh = (l >> 4) << 4;                 // byte-column half: 0 or 16
    uint32_t xorv = (uint32_t)(lm & 7) << 4;
    uint32_t lob0 = ((uint32_t)lh) ^ xorv;  // ks=0 column offset
    uint32_t arow[4], brow[4];
#pragma unroll
    for (int mt = 0; mt < 4; mt++) arow[mt] = (uint32_t)(wm * 64 + mt * 16 + lm) * 128;
#pragma unroll
    for (int bt = 0; bt < 4; bt++) brow[bt] = (uint32_t)(wn * 64 + bt * 16 + lm) * 128;

    float acc[4][8][4] = {};
    uint32_t afr[4][4];            // A fragments, WAR-reused
    uint32_t bfr[2][4][4];         // B fragments, double-buffered [buf][bt][]

    // epilogue lane constants
    int g8 = l >> 2;
    int q = (l & 3) * 2;

    // prologue: wait first chunk, load its ks=0 fragments
    uint32_t stA = sb + OFF_TILE;
    uint32_t stB = stA + 2 * A_SUB;
    mbar_wait(sb + OFF_FULL(0), 0);
#pragma unroll
    for (int mt = 0; mt < 4; mt++) ldsm4(afr[mt], stA + arow[mt] + lob0);
#pragma unroll
    for (int bt = 0; bt < 4; bt++) ldsm4(bfr[0][bt], stB + brow[bt] + lob0);

#pragma unroll 1
    for (int i = 0; i < ntiles; i++) {
        bool more = (i + 1 < ntiles);
        int tl2 = tl + NCTA;
        int nm0 = (tl2 >> 4) * TILE_M;      // next tile coords (unused if !more)
        int nn0 = (tl2 & 15) * TILE_N;

#pragma unroll 1
        for (int c = 0; c < CPT; c++) {
            int st = c & 1;
            uint32_t ph = (uint32_t)((c >> 1) & 1);

#pragma unroll
            for (int ks = 0; ks < 8; ks++) {
                int cb = ks & 1, nb = cb ^ 1;
                int kn = ks + 1;
                uint32_t subA = (uint32_t)(kn >> 2) * A_SUB;
                uint32_t subB = (uint32_t)(kn >> 2) * B_SUB;
                uint32_t lobn = ((uint32_t)(lh + (kn & 3) * 32)) ^ xorv;

                if (ks < 7) {
#pragma unroll
                    for (int bt = 0; bt < 4; bt++)
                        ldsm4(bfr[nb][bt], stB + subB + brow[bt] + lobn);
                } else {
                    if (l == 0) mbar_arrive(sb + OFF_EMPTY(st));
                }

#pragma unroll
                for (int mt = 0; mt < 4; mt++) {
#pragma unroll
                    for (int nt = 0; nt < 8; nt++) {
                        int bt = nt >> 1, se = nt & 1;
                        mma_f16(acc[mt][nt], afr[mt], bfr[cb][bt][se], bfr[cb][bt][se + 2]);
                    }
                    if (ks < 7) ldsm4(afr[mt], stA + subA + arow[mt] + lobn);
                }
            }

            // producer: refill stage st with chunk c+2 (possibly next tile)
            if (tid == 0) {
                int tc = c + 2;
                if (tc < CPT) {
                    mbar_wait(sb + OFF_EMPTY(st), ph);
                    issue_chunk(sb, st, tc * TILE_K, m0, n0, &map_a, &map_b);
                } else if (more) {
                    mbar_wait(sb + OFF_EMPTY(st), ph);
                    issue_chunk(sb, st, (tc - CPT) * TILE_K, nm0, nn0, &map_a, &map_b);
                }
            }

            // same-tile boundary: wait next chunk full, load ks=0 fragments
            if (c + 1 < CPT) {
                int st2 = (c + 1) & 1;
                uint32_t ph2 = (uint32_t)(((c + 1) >> 1) & 1);
                stA = sb + OFF_TILE + st2 * STAGE_BYTES;
                stB = stA + 2 * A_SUB;
                mbar_wait(sb + OFF_FULL(st2), ph2);
#pragma unroll
                for (int mt = 0; mt < 4; mt++) ldsm4(afr[mt], stA + arow[mt] + lob0);
#pragma unroll
                for (int bt = 0; bt < 4; bt++) ldsm4(bfr[0][bt], stB + brow[bt] + lob0);
            }
        }

        // epilogue for this tile (next tile's TMA already in flight)
#pragma unroll
        for (int mt = 0; mt < 4; mt++) {
            int r0 = m0 + wm * 64 + mt * 16 + g8;
#pragma unroll
            for (int nt = 0; nt < 8; nt++) {
                int col = n0 + wn * 64 + nt * 8 + q;
                float2 bv = *reinterpret_cast<const float2*>(bias + col);
                float2 v0, v1;
                v0.x = acc[mt][nt][0] + bv.x;
                v0.y = acc[mt][nt][1] + bv.y;
                v1.x = acc[mt][nt][2] + bv.x;
                v1.y = acc[mt][nt][3] + bv.y;
                *reinterpret_cast<float2*>(out + (size_t)r0 * NN + col) = v0;
                *reinterpret_cast<float2*>(out + (size_t)(r0 + 8) * NN + col) = v1;
                acc[mt][nt][0] = 0.f; acc[mt][nt][1] = 0.f;
                acc[mt][nt][2] = 0.f; acc[mt][nt][3] = 0.f;
            }
        }

        // advance to next tile: stage 0, parity 0 (tile-invariant)
        tl = tl2; m0 = nm0; n0 = nn0;
        if (more) {
            stA = sb + OFF_TILE;
            stB = stA + 2 * A_SUB;
            mbar_wait(sb + OFF_FULL(0), 0);
#pragma unroll
            for (int mt = 0; mt < 4; mt++) ldsm4(afr[mt], stA + arow[mt] + lob0);
#pragma unroll
            for (int bt = 0; bt < 4; bt++) ldsm4(bfr[0][bt], stB + brow[bt] + lob0);
        }
    }
}

// ---------------- host launch ---------------------------------------------
typedef CUresult (*PFN_encodeTiled)(CUtensorMap*, CUtensorMapDataType, cuuint32_t,
                                    void*, const cuuint64_t*, const cuuint64_t*,
                                    const cuuint32_t*, const cuuint32_t*,
                                    CUtensorMapInterleave, CUtensorMapSwizzle,
                                    CUtensorMapL2promotion, CUtensorMapFloatOOBfill);

static void encode_map(PFN_encodeTiled enc, CUtensorMap* m, void* ptr,
                       unsigned long long d0, unsigned long long d1,
                       unsigned b0, unsigned b1) {
    cuuint64_t dims[3]    = {d0, d1, 1};
    cuuint64_t strides[2] = {d0 * 2ull, d0 * d1 * 2ull};   // fp16
    cuuint32_t box[3]     = {b0, b1, 1};
    cuuint32_t es[3]      = {1, 1, 1};
    enc(m, CU_TENSOR_MAP_DATA_TYPE_FLOAT16, 3, ptr, dims, strides, box, es,
        CU_TENSOR_MAP_INTERLEAVE_NONE, CU_TENSOR_MAP_SWIZZLE_128B,
        CU_TENSOR_MAP_L2_PROMOTION_L2_128B, CU_TENSOR_MAP_FLOAT_OOB_FILL_NONE);
}

extern "C" void kernel_launch(void* const* d_in, const int* in_sizes, int n_in,
                              void* d_out, int out_size) {
    const float* x    = (const float*)d_in[0];
    const float* wq   = (const float*)d_in[1];
    const float* ws   = (const float*)d_in[2];
    const float* bias = (const float*)d_in[3];
    float* out = (float*)d_out;

    void *pxh, *pwh;
    cudaGetSymbolAddress(&pxh, g_xh);
    cudaGetSymbolAddress(&pwh, g_wh);

    prep_all<<<PREPT / 256, 256>>>((const float4*)x, (const float4*)wq, ws,
                                   (uint4*)pxh, (uint4*)pwh);

    void* fn = nullptr;
    cudaDriverEntryPointQueryResult qr;
    cudaGetDriverEntryPointByVersion("cuTensorMapEncodeTiled", &fn, 12000,
                                     cudaEnableDefault, &qr);
    PFN_encodeTiled enc = (PFN_encodeTiled)fn;

    CUtensorMap ma, mb;
    encode_map(enc, &ma, pxh, KK, TT, 64, TILE_M);
    encode_map(enc, &mb, pwh, KK, NN, 64, TILE_N);

    cudaFuncSetAttribute(gemm_kernel, cudaFuncAttributeMaxDynamicSharedMemorySize,
                         SMEM_TOTAL);
    gemm_kernel<<<NCTA, 256, SMEM_TOTAL>>>(ma, mb, bias, out);
}